// round 14
// baseline (speedup 1.0000x reference)
#include <cuda_runtime.h>
#include <cuda_bf16.h>

// Fixed-shape problem: N=2000 nodes, F=2, HIDDEN=64, K=3, G=256 graphs, E~7998 edges
#define NN    2000
#define EMAXS 8192
#define HID   64
#define TPB   1024
#define HALF  512

typedef unsigned long long ull;

// ---------------- f32x2 packed-math helpers ----------------
__device__ __forceinline__ ull pk2(float lo, float hi) {
    ull r; asm("mov.b64 %0,{%1,%2};" : "=l"(r) : "f"(lo), "f"(hi)); return r;
}
__device__ __forceinline__ void upk2(ull v, float& lo, float& hi) {
    asm("mov.b64 {%0,%1}, %2;" : "=f"(lo), "=f"(hi) : "l"(v));
}
__device__ __forceinline__ ull fma2v(ull a, ull b, ull c) {
    ull d; asm("fma.rn.f32x2 %0, %1, %2, %3;" : "=l"(d) : "l"(a), "l"(b), "l"(c)); return d;
}
__device__ __forceinline__ ull add2v(ull a, ull b) {
    ull d; asm("add.rn.f32x2 %0, %1, %2;" : "=l"(d) : "l"(a), "l"(b)); return d;
}
#define BAR_HALF(id) asm volatile("bar.sync %0, %1;" :: "r"(id), "r"(HALF) : "memory")

// per-half gather: pout[n] = (useAdd? add[n]:0) + A*pin ; single graph, unroll-2
__device__ __forceinline__ void gather_half(const ull* __restrict__ pin,
                                            ull* __restrict__ pout,
                                            const ull* __restrict__ add, bool useAdd,
                                            const int2* __restrict__ sedge,
                                            const int* __restrict__ sptr, int ht) {
    const char* pinc = (const char*)pin;
    #pragma unroll 1
    for (int n = ht; n < NN; n += HALF) {
        int b = sptr[n], e = sptr[n + 1];
        ull a0 = useAdd ? add[n] : 0ull;
        ull c0 = 0ull;
        int q = b;
        #pragma unroll 1
        for (; q + 2 <= e; q += 2) {
            int2 e0 = sedge[q];
            int2 e1 = sedge[q + 1];
            ull v0 = *(const ull*)(pinc + e0.x);
            ull v1 = *(const ull*)(pinc + e1.x);
            float w0 = __int_as_float(e0.y);
            float w1 = __int_as_float(e1.y);
            a0 = fma2v(v0, pk2(w0, w0), a0);
            c0 = fma2v(v1, pk2(w1, w1), c0);
        }
        if (q < e) {
            int2 e0 = sedge[q];
            ull v0 = *(const ull*)(pinc + e0.x);
            float w0 = __int_as_float(e0.y);
            a0 = fma2v(v0, pk2(w0, w0), a0);
        }
        pout[n] = add2v(a0, c0);
    }
}

// smem: pbA0..3, pbB0..3 (ull[NN] each) | sedge | w1q/w2q/b1s | sperm | sptr
#define SMEM_BYTES (8 * NN * 8 + EMAXS * 8 + 2048 + 2048 + 256 + NN * 4 + (NN + 1) * 4)

__global__ __launch_bounds__(TPB, 1)
void k_main(const float* __restrict__ x,
            const int* __restrict__ row, const int* __restrict__ col,
            const float* __restrict__ ew,
            const float* __restrict__ W1, const float* __restrict__ b1,
            const float* __restrict__ W2, const float* __restrict__ b2,
            float* __restrict__ out, int G, int E) {
    extern __shared__ float sm[];
    ull* pbA0 = (ull*)sm;
    ull* pbA1 = pbA0 + NN;
    ull* pbA2 = pbA1 + NN;
    ull* pbA3 = pbA2 + NN;
    ull* pbB0 = pbA3 + NN;
    ull* pbB1 = pbB0 + NN;
    ull* pbB2 = pbB1 + NN;
    ull* pbB3 = pbB2 + NN;
    int2*  sedge = (int2*)(pbB3 + NN);
    float* w1q = (float*)(sedge + EMAXS);   // [32 jp][8 i][2 half]
    float* w2q = w1q + 512;                 // [32 jp][2 jj][8 c]
    float* b1s = w2q + 512;
    int*   sperm = (int*)(b1s + 64);
    int*   sptr  = sperm + NN;

    // prepass overlays (dead once staging begins)
    float* sdeg = (float*)pbA0;
    int*   scnt = (int*)pbA1;
    int*   sinv = (int*)pbA2;
    int*   scur = (int*)pbA3;
    int*   hist = (int*)pbB0;
    int*   hoff = hist + 64;
    int*   wsum = hoff + 64;

    const int t  = threadIdx.x;
    const int bs = blockDim.x;
    if (E > EMAXS) return;

    // ================= in-CTA prepass (identical in every CTA) =================
    for (int i = t; i < NN; i += bs) { sdeg[i] = 0.f; scnt[i] = 0; }
    if (t < 64) hist[t] = 0;
    __syncthreads();

    for (int e = t; e < E; e += bs) {
        int c = col[e];
        atomicAdd(&sdeg[c], ew[e]);
        atomicAdd(&scnt[c], 1);
    }
    __syncthreads();

    for (int n = t; n < NN; n += bs) {
        int d = scnt[n]; if (d > 63) d = 63;
        atomicAdd(&hist[d], 1);
    }
    __syncthreads();
    if (t == 0) {
        int run = 0;
        for (int d = 0; d < 64; d++) { hoff[d] = run; run += hist[d]; }
    }
    __syncthreads();

    for (int n = t; n < NN; n += bs) {
        int d = scnt[n]; int dc = (d > 63) ? 63 : d;
        int slot = atomicAdd(&hoff[dc], 1);
        sinv[n] = slot;
        sperm[slot] = n;
        scur[slot] = d;
    }
    __syncthreads();

    {   // exclusive scan of slot-degrees -> sptr, scur as cursors
        int i0 = 2 * t, i1 = 2 * t + 1;
        int a0 = (i0 < NN) ? scur[i0] : 0;
        int a1 = (i1 < NN) ? scur[i1] : 0;
        int tot = a0 + a1;
        int lane = t & 31, wid = t >> 5;
        int v = tot;
        #pragma unroll
        for (int o = 1; o < 32; o <<= 1) {
            int u = __shfl_up_sync(0xFFFFFFFFu, v, o);
            if (lane >= o) v += u;
        }
        if (lane == 31) wsum[wid] = v;
        __syncthreads();
        if (wid == 0) {
            int w = wsum[lane];
            #pragma unroll
            for (int o = 1; o < 32; o <<= 1) {
                int u = __shfl_up_sync(0xFFFFFFFFu, w, o);
                if (lane >= o) w += u;
            }
            wsum[lane] = w;
        }
        __syncthreads();
        int base = v - tot + (wid ? wsum[wid - 1] : 0);
        if (i0 < NN) sptr[i0] = base;
        if (i1 < NN) sptr[i1] = base + a0;
        if (t == 0)  sptr[NN] = E;
        __syncthreads();
        if (i0 < NN) scur[i0] = sptr[i0];
        if (i1 < NN) scur[i1] = sptr[i1];
    }
    __syncthreads();

    for (int e = t; e < E; e += bs) {
        int r = row[e], c = col[e];
        float dr = sdeg[r], dc = sdeg[c];
        float ir = (dr > 0.f) ? rsqrtf(dr) : 0.f;
        float ic = (dc > 0.f) ? rsqrtf(dc) : 0.f;
        float nrm = ir * ew[e] * ic;
        int p = atomicAdd(&scur[sinv[c]], 1);
        sedge[p] = make_int2(sinv[r] * 8, __float_as_int(nrm));   // BYTE offset (ull stride)
    }
    __syncthreads();
    // ================= prepass done; overlays now dead =================

    const int gA = 2 * blockIdx.x;
    int gB = gA + 1; bool hasB = (gB < G); if (!hasB) gB = gA;

    // stage packed weights (any time before the dense-phase full barrier)
    for (int i = t; i < 512; i += bs) {
        int jp = i >> 4, rem = i & 15;
        {   int ii = rem >> 1, half = rem & 1;
            w1q[i] = W1[ii * HID + 2 * jp + half]; }
        {   int jj = rem >> 3, c = rem & 7;
            int j = 2 * jp + jj;
            w2q[i] = W2[(c >> 1) * (HID * 2) + j * 2 + (c & 1)]; }
    }
    for (int i = t; i < HID; i += bs) b1s[i] = b1[i];

    const ull* xgA = (const ull*)(x + (size_t)gA * 2 * NN);
    const ull* xgB = (const ull*)(x + (size_t)gB * 2 * NN);

    // ---- split halves: warps 0-15 -> graph A (bar 1), warps 16-31 -> graph B (bar 2)
    if (t < HALF) {
        const int ht = t;
        for (int s = ht; s < NN; s += HALF) pbA0[s] = __ldg(&xgA[sperm[s]]);
        BAR_HALF(1);
        gather_half(pbA0, pbA1, pbA0, false, sedge, sptr, ht); BAR_HALF(1);
        gather_half(pbA1, pbA2, pbA0, false, sedge, sptr, ht); BAR_HALF(1);
        gather_half(pbA2, pbA3, pbA0, false, sedge, sptr, ht);
    } else {
        const int ht = t - HALF;
        for (int s = ht; s < NN; s += HALF) pbB0[s] = __ldg(&xgB[sperm[s]]);
        BAR_HALF(2);
        gather_half(pbB0, pbB1, pbB0, false, sedge, sptr, ht); BAR_HALF(2);
        gather_half(pbB1, pbB2, pbB0, false, sedge, sptr, ht); BAR_HALF(2);
        gather_half(pbB2, pbB3, pbB0, false, sedge, sptr, ht);
    }
    __syncthreads();   // join: dense needs both graphs

    // ---- dense per-node sandwich (R13 inner loop; split-buffer I/O) ----
    {
        const ulonglong2* w1v = (const ulonglong2*)w1q;
        const ulonglong2* w2v = (const ulonglong2*)w2q;
        const ull* b1v = (const ull*)b1s;
        for (int n = t; n < NN; n += bs) {
            ull aA0 = pbA0[n], aA1x = pbA1[n], aA2x = pbA2[n], aA3x = pbA3[n];
            ull aB0 = pbB0[n], aB1x = pbB1[n], aB2x = pbB2[n], aB3x = pbB3[n];
            float f0, f1;
            upk2(aA0,  f0, f1); ull pA0 = pk2(f0, f0), pA1 = pk2(f1, f1);
            upk2(aA1x, f0, f1); ull pA2 = pk2(f0, f0), pA3 = pk2(f1, f1);
            upk2(aA2x, f0, f1); ull pA4 = pk2(f0, f0), pA5 = pk2(f1, f1);
            upk2(aA3x, f0, f1); ull pA6 = pk2(f0, f0), pA7 = pk2(f1, f1);
            upk2(aB0,  f0, f1); ull pB0 = pk2(f0, f0), pB1 = pk2(f1, f1);
            upk2(aB1x, f0, f1); ull pB2 = pk2(f0, f0), pB3 = pk2(f1, f1);
            upk2(aB2x, f0, f1); ull pB4 = pk2(f0, f0), pB5 = pk2(f1, f1);
            upk2(aB3x, f0, f1); ull pB6 = pk2(f0, f0), pB7 = pk2(f1, f1);
            ull mA0 = 0, mA1 = 0, mA2 = 0, mA3 = 0;
            ull mB0 = 0, mB1 = 0, mB2 = 0, mB3 = 0;
            #pragma unroll 4
            for (int jp = 0; jp < 32; jp++) {
                ulonglong2 qa = w1v[jp * 4 + 0], qb = w1v[jp * 4 + 1];
                ulonglong2 qc = w1v[jp * 4 + 2], qd = w1v[jp * 4 + 3];
                ull bb = b1v[jp];
                ull hA = bb, hB = bb;
                hA = fma2v(pA0, qa.x, hA); hA = fma2v(pA1, qa.y, hA);
                hA = fma2v(pA2, qb.x, hA); hA = fma2v(pA3, qb.y, hA);
                hA = fma2v(pA4, qc.x, hA); hA = fma2v(pA5, qc.y, hA);
                hA = fma2v(pA6, qd.x, hA); hA = fma2v(pA7, qd.y, hA);
                hB = fma2v(pB0, qa.x, hB); hB = fma2v(pB1, qa.y, hB);
                hB = fma2v(pB2, qb.x, hB); hB = fma2v(pB3, qb.y, hB);
                hB = fma2v(pB4, qc.x, hB); hB = fma2v(pB5, qc.y, hB);
                hB = fma2v(pB6, qd.x, hB); hB = fma2v(pB7, qd.y, hB);
                float hA0, hA1, hB0, hB1;
                upk2(hA, hA0, hA1); upk2(hB, hB0, hB1);
                hA0 = fmaxf(hA0, 0.f); hA1 = fmaxf(hA1, 0.f);
                hB0 = fmaxf(hB0, 0.f); hB1 = fmaxf(hB1, 0.f);
                ull hA0p = pk2(hA0, hA0), hA1p = pk2(hA1, hA1);
                ull hB0p = pk2(hB0, hB0), hB1p = pk2(hB1, hB1);
                ulonglong2 ra = w2v[jp * 4 + 0], rb = w2v[jp * 4 + 1];
                ulonglong2 rc = w2v[jp * 4 + 2], rd = w2v[jp * 4 + 3];
                mA0 = fma2v(hA0p, ra.x, mA0); mA1 = fma2v(hA0p, ra.y, mA1);
                mA2 = fma2v(hA0p, rb.x, mA2); mA3 = fma2v(hA0p, rb.y, mA3);
                mA0 = fma2v(hA1p, rc.x, mA0); mA1 = fma2v(hA1p, rc.y, mA1);
                mA2 = fma2v(hA1p, rd.x, mA2); mA3 = fma2v(hA1p, rd.y, mA3);
                mB0 = fma2v(hB0p, ra.x, mB0); mB1 = fma2v(hB0p, ra.y, mB1);
                mB2 = fma2v(hB0p, rb.x, mB2); mB3 = fma2v(hB0p, rb.y, mB3);
                mB0 = fma2v(hB1p, rc.x, mB0); mB1 = fma2v(hB1p, rc.y, mB1);
                mB2 = fma2v(hB1p, rd.x, mB2); mB3 = fma2v(hB1p, rd.y, mB3);
            }
            pbA0[n] = mA0; pbA1[n] = mA1; pbA2[n] = mA2; pbA3[n] = mA3;
            pbB0[n] = mB0; pbB1[n] = mB1; pbB2[n] = mB2; pbB3[n] = mB3;
        }
    }
    __syncthreads();   // split halves resume

    float b20 = b2[0], b21 = b2[1];
    if (t < HALF) {
        const int ht = t;
        gather_half(pbA3, pbA2, pbA2, true, sedge, sptr, ht); BAR_HALF(1);   // m2 + A m3
        gather_half(pbA2, pbA1, pbA1, true, sedge, sptr, ht); BAR_HALF(1);   // m1 + A s
        // epilogue A: out = x + m0 + A pbA1 + b2
        float2* ogA = (float2*)out + (size_t)gA * NN;
        const char* pinc = (const char*)pbA1;
        #pragma unroll 1
        for (int n = ht; n < NN; n += HALF) {
            int node = sperm[n];
            ull xA = __ldg(&xgA[node]);
            int b = sptr[n], e = sptr[n + 1];
            ull a0 = pbA0[n], c0 = 0ull;
            int q = b;
            #pragma unroll 1
            for (; q + 2 <= e; q += 2) {
                int2 e0 = sedge[q], e1 = sedge[q + 1];
                ull v0 = *(const ull*)(pinc + e0.x);
                ull v1 = *(const ull*)(pinc + e1.x);
                float w0 = __int_as_float(e0.y), w1 = __int_as_float(e1.y);
                a0 = fma2v(v0, pk2(w0, w0), a0);
                c0 = fma2v(v1, pk2(w1, w1), c0);
            }
            if (q < e) {
                int2 e0 = sedge[q];
                ull v0 = *(const ull*)(pinc + e0.x);
                float w0 = __int_as_float(e0.y);
                a0 = fma2v(v0, pk2(w0, w0), a0);
            }
            a0 = add2v(a0, c0);
            float ox, oy, xl, xh;
            upk2(a0, ox, oy); upk2(xA, xl, xh);
            ogA[node] = make_float2(xl + ox + b20, xh + oy + b21);
        }
    } else {
        const int ht = t - HALF;
        gather_half(pbB3, pbB2, pbB2, true, sedge, sptr, ht); BAR_HALF(2);
        gather_half(pbB2, pbB1, pbB1, true, sedge, sptr, ht); BAR_HALF(2);
        float2* ogB = (float2*)out + (size_t)gB * NN;
        const char* pinc = (const char*)pbB1;
        #pragma unroll 1
        for (int n = ht; n < NN; n += HALF) {
            int node = sperm[n];
            ull xB = __ldg(&xgB[node]);
            int b = sptr[n], e = sptr[n + 1];
            ull a0 = pbB0[n], c0 = 0ull;
            int q = b;
            #pragma unroll 1
            for (; q + 2 <= e; q += 2) {
                int2 e0 = sedge[q], e1 = sedge[q + 1];
                ull v0 = *(const ull*)(pinc + e0.x);
                ull v1 = *(const ull*)(pinc + e1.x);
                float w0 = __int_as_float(e0.y), w1 = __int_as_float(e1.y);
                a0 = fma2v(v0, pk2(w0, w0), a0);
                c0 = fma2v(v1, pk2(w1, w1), c0);
            }
            if (q < e) {
                int2 e0 = sedge[q];
                ull v0 = *(const ull*)(pinc + e0.x);
                float w0 = __int_as_float(e0.y);
                a0 = fma2v(v0, pk2(w0, w0), a0);
            }
            a0 = add2v(a0, c0);
            if (hasB) {
                float ox, oy, xl, xh;
                upk2(a0, ox, oy); upk2(xB, xl, xh);
                ogB[node] = make_float2(xl + ox + b20, xh + oy + b21);
            }
        }
    }
}

// ---------------- launcher ----------------
extern "C" void kernel_launch(void* const* d_in, const int* in_sizes, int n_in,
                              void* d_out, int out_size) {
    const float* x   = (const float*)d_in[0];
    const int*   row = (const int*)  d_in[1];
    const int*   col = (const int*)  d_in[2];
    const float* ew  = (const float*)d_in[3];
    const float* W1  = (const float*)d_in[4];
    const float* b1  = (const float*)d_in[5];
    const float* W2  = (const float*)d_in[6];
    const float* b2  = (const float*)d_in[7];

    const int E = in_sizes[1];
    const int G = in_sizes[0] / (2 * NN);
    const int nCta = (G + 1) / 2;

    cudaFuncSetAttribute(k_main, cudaFuncAttributeMaxDynamicSharedMemorySize, SMEM_BYTES);

    k_main<<<nCta, TPB, SMEM_BYTES>>>(x, row, col, ew, W1, b1, W2, b2,
                                      (float*)d_out, G, E);
}

// round 15
// speedup vs baseline: 1.1330x; 1.1330x over previous
#include <cuda_runtime.h>
#include <cuda_bf16.h>

// Fixed-shape problem: N=2000 nodes, F=2, HIDDEN=64, K=3, G=256 graphs, E~7998 edges
#define NN    2000
#define EMAXS 8192           // max real edges supported
#define EPAD  10240          // padded capacity (E + <=1 dummy per node)
#define HID   64
#define TPB   1024

typedef unsigned long long ull;
typedef unsigned short u16;
typedef unsigned int uint32;

// ---------------- f32x2 packed-math helpers (sm_100+ PTX) ----------------
__device__ __forceinline__ ull pk2(float lo, float hi) {
    ull r; asm("mov.b64 %0,{%1,%2};" : "=l"(r) : "f"(lo), "f"(hi)); return r;
}
__device__ __forceinline__ void upk2(ull v, float& lo, float& hi) {
    asm("mov.b64 {%0,%1}, %2;" : "=f"(lo), "=f"(hi) : "l"(v));
}
__device__ __forceinline__ ull fma2v(ull a, ull b, ull c) {
    ull d; asm("fma.rn.f32x2 %0, %1, %2, %3;" : "=l"(d) : "l"(a), "l"(b), "l"(c)); return d;
}
__device__ __forceinline__ ull add2v(ull a, ull b) {
    ull d; asm("add.rn.f32x2 %0, %1, %2;" : "=l"(d) : "l"(a), "l"(b)); return d;
}

// ---------------- single fused kernel: one CTA per TWO graphs ----------------
// smem: pb0..pb3 (ulonglong2[NN]) | sedge_w f32[EPAD] | sedge_s u16[EPAD] |
//       w1q/w2q/b1s | sperm | sptr
// Node buffers: ulonglong2 per node = { graphA pair(f0,f1), graphB pair(f0,f1) }
#define SMEM_BYTES (4 * NN * 16 + EPAD * 4 + EPAD * 2 + 2048 + 2048 + 256 + NN * 4 + (NN + 1) * 4)

__global__ __launch_bounds__(TPB, 1)
void k_main(const float* __restrict__ x,
            const int* __restrict__ row, const int* __restrict__ col,
            const float* __restrict__ ew,
            const float* __restrict__ W1, const float* __restrict__ b1,
            const float* __restrict__ W2, const float* __restrict__ b2,
            float* __restrict__ out, int G, int E) {
    extern __shared__ float sm[];
    ulonglong2* pb0 = (ulonglong2*)sm;
    ulonglong2* pb1 = pb0 + NN;
    ulonglong2* pb2 = pb1 + NN;
    ulonglong2* pb3 = pb2 + NN;
    float* sedge_w = (float*)(pb3 + NN);       // [EPAD] gcn_norm weights (8B-aligned)
    u16*   sedge_s = (u16*)(sedge_w + EPAD);   // [EPAD] src byte offsets (slot*16)
    float* w1q = (float*)(sedge_s + EPAD);     // [32 jp][8 i][2 half]
    float* w2q = w1q + 512;                    // [32 jp][2 jj][8 c]
    float* b1s = w2q + 512;
    int*   sperm = (int*)(b1s + 64);           // slot -> node
    int*   sptr  = sperm + NN;                 // padded CSR row pointers [NN+1]

    // ---- prepass overlays (dead once staging begins) ----
    float* sdeg = (float*)pb0;                 // [NN]
    int*   scnt = (int*)pb1;                   // [NN]
    int*   sinv = (int*)pb2;                   // [NN] node -> slot
    int*   scur = (int*)pb3;                   // [NN] slot degree / cursor
    int*   hist = (int*)pb0 + 2048;            // [64]
    int*   hoff = hist + 64;                   // [64]
    int*   wsum = hoff + 64;                   // [32]

    const int t  = threadIdx.x;
    const int bs = blockDim.x;
    if (E > EMAXS) return;   // shape guard (never taken for this problem)

    // ================= in-CTA prepass (identical in every CTA) =================
    for (int i = t; i < NN; i += bs) { sdeg[i] = 0.f; scnt[i] = 0; }
    if (t < 64) hist[t] = 0;
    __syncthreads();

    for (int e = t; e < E; e += bs) {
        int c = col[e];
        atomicAdd(&sdeg[c], ew[e]);
        atomicAdd(&scnt[c], 1);
    }
    __syncthreads();

    for (int n = t; n < NN; n += bs) {
        int d = scnt[n]; if (d > 63) d = 63;
        atomicAdd(&hist[d], 1);
    }
    __syncthreads();
    if (t == 0) {
        int run = 0;
        for (int d = 0; d < 64; d++) { hoff[d] = run; run += hist[d]; }
    }
    __syncthreads();

    for (int n = t; n < NN; n += bs) {
        int d = scnt[n]; int dc = (d > 63) ? 63 : d;
        int slot = atomicAdd(&hoff[dc], 1);
        sinv[n] = slot;
        sperm[slot] = n;
        scur[slot] = d;                        // real degree per slot
    }
    __syncthreads();

    {   // exclusive scan of EVEN-PADDED slot-degrees -> sptr; scur = cursors
        int i0 = 2 * t, i1 = 2 * t + 1;
        int a0 = (i0 < NN) ? ((scur[i0] + 1) & ~1) : 0;   // pad to even
        int a1 = (i1 < NN) ? ((scur[i1] + 1) & ~1) : 0;
        int tot = a0 + a1;
        int lane = t & 31, wid = t >> 5;
        int v = tot;
        #pragma unroll
        for (int o = 1; o < 32; o <<= 1) {
            int u = __shfl_up_sync(0xFFFFFFFFu, v, o);
            if (lane >= o) v += u;
        }
        if (lane == 31) wsum[wid] = v;
        __syncthreads();
        if (wid == 0) {
            int w = wsum[lane];
            #pragma unroll
            for (int o = 1; o < 32; o <<= 1) {
                int u = __shfl_up_sync(0xFFFFFFFFu, w, o);
                if (lane >= o) w += u;
            }
            wsum[lane] = w;
        }
        __syncthreads();
        int base = v - tot + (wid ? wsum[wid - 1] : 0);
        if (i0 < NN) sptr[i0] = base;
        if (i1 < NN) sptr[i1] = base + a0;
        if (t == 0)  sptr[NN] = wsum[31];      // padded total
        __syncthreads();
        if (i0 < NN) scur[i0] = sptr[i0];
        if (i1 < NN) scur[i1] = sptr[i1];
    }
    __syncthreads();

    // scatter real edges into padded slot-space CSR
    for (int e = t; e < E; e += bs) {
        int r = row[e], c = col[e];
        float dr = sdeg[r], dc = sdeg[c];
        float ir = (dr > 0.f) ? rsqrtf(dr) : 0.f;
        float ic = (dc > 0.f) ? rsqrtf(dc) : 0.f;
        float nrm = ir * ew[e] * ic;
        int p = atomicAdd(&scur[sinv[c]], 1);
        sedge_s[p] = (u16)(sinv[r] * 16);      // byte offset into ulonglong2 buffer
        sedge_w[p] = nrm;
    }
    __syncthreads();

    // fill <=1 dummy pad edge per node (w=0 -> contributes nothing)
    for (int n = t; n < NN; n += bs) {
        int p = scur[n];
        if (p < sptr[n + 1]) { sedge_s[p] = 0; sedge_w[p] = 0.f; }
    }
    __syncthreads();
    // ================= prepass done; overlays now dead =================

    const int gA = 2 * blockIdx.x;
    int gB = gA + 1; bool hasB = (gB < G); if (!hasB) gB = gA;

    // stage packed weights
    for (int i = t; i < 512; i += bs) {
        int jp = i >> 4, rem = i & 15;
        {   int ii = rem >> 1, half = rem & 1;
            w1q[i] = W1[ii * HID + 2 * jp + half]; }
        {   int jj = rem >> 3, c = rem & 7;
            int j = 2 * jp + jj;
            w2q[i] = W2[(c >> 1) * (HID * 2) + j * 2 + (c & 1)]; }
    }
    for (int i = t; i < HID; i += bs) b1s[i] = b1[i];

    // stage x into slot space (permuted gather, both graphs) -> pb0
    const ull* xgA = (const ull*)(x + (size_t)gA * 2 * NN);
    const ull* xgB = (const ull*)(x + (size_t)gB * 2 * NN);
    for (int s = t; s < NN; s += bs) {
        int node = sperm[s];
        pb0[s] = make_ulonglong2(__ldg(&xgA[node]), __ldg(&xgB[node]));
    }
    __syncthreads();

    // ---- gather: u16-pair offsets + f32-pair weights, even length, no tail ----
    #define GATHER(PIN, POUT, ADD, USE_ADD)                                    \
    {   const char* pinc = (const char*)(PIN);                                 \
        _Pragma("unroll 1")                                                    \
        for (int n = t; n < NN; n += bs) {                                     \
            int b = sptr[n], e = sptr[n + 1];                                  \
            ull a0 = 0ull, a1 = 0ull, c0 = 0ull, c1 = 0ull;                    \
            if (USE_ADD) { ulonglong2 z = (ADD)[n]; a0 = z.x; a1 = z.y; }      \
            _Pragma("unroll 1")                                                \
            for (int q = b; q < e; q += 2) {                                   \
                uint32 ss = *(const uint32*)(sedge_s + q);                     \
                float2 wv = *(const float2*)(sedge_w + q);                     \
                ulonglong2 v0 = *(const ulonglong2*)(pinc + (ss & 0xFFFFu));   \
                ulonglong2 v1 = *(const ulonglong2*)(pinc + (ss >> 16));       \
                ull ww0 = pk2(wv.x, wv.x), ww1 = pk2(wv.y, wv.y);              \
                a0 = fma2v(v0.x, ww0, a0); a1 = fma2v(v0.y, ww0, a1);          \
                c0 = fma2v(v1.x, ww1, c0); c1 = fma2v(v1.y, ww1, c1);          \
            }                                                                  \
            a0 = add2v(a0, c0); a1 = add2v(a1, c1);                            \
            (POUT)[n] = make_ulonglong2(a0, a1);                               \
        }                                                                      \
    }

    // layer-1 hops
    GATHER(pb0, pb1, pb0, false); __syncthreads();
    GATHER(pb1, pb2, pb0, false); __syncthreads();
    GATHER(pb2, pb3, pb0, false); __syncthreads();

    // ---- dense per-node sandwich (verbatim R13): [8] -> 64 (relu) -> [8] ----
    {
        const ulonglong2* w1v = (const ulonglong2*)w1q;
        const ulonglong2* w2v = (const ulonglong2*)w2q;
        const ull* b1v = (const ull*)b1s;
        for (int n = t; n < NN; n += bs) {
            ulonglong2 a0 = pb0[n], a1 = pb1[n], a2 = pb2[n], a3 = pb3[n];
            float f0, f1;
            upk2(a0.x, f0, f1); ull pA0 = pk2(f0, f0), pA1 = pk2(f1, f1);
            upk2(a1.x, f0, f1); ull pA2 = pk2(f0, f0), pA3 = pk2(f1, f1);
            upk2(a2.x, f0, f1); ull pA4 = pk2(f0, f0), pA5 = pk2(f1, f1);
            upk2(a3.x, f0, f1); ull pA6 = pk2(f0, f0), pA7 = pk2(f1, f1);
            upk2(a0.y, f0, f1); ull pB0 = pk2(f0, f0), pB1 = pk2(f1, f1);
            upk2(a1.y, f0, f1); ull pB2 = pk2(f0, f0), pB3 = pk2(f1, f1);
            upk2(a2.y, f0, f1); ull pB4 = pk2(f0, f0), pB5 = pk2(f1, f1);
            upk2(a3.y, f0, f1); ull pB6 = pk2(f0, f0), pB7 = pk2(f1, f1);
            ull mA0 = 0, mA1 = 0, mA2 = 0, mA3 = 0;
            ull mB0 = 0, mB1 = 0, mB2 = 0, mB3 = 0;
            #pragma unroll 4
            for (int jp = 0; jp < 32; jp++) {
                ulonglong2 qa = w1v[jp * 4 + 0], qb = w1v[jp * 4 + 1];
                ulonglong2 qc = w1v[jp * 4 + 2], qd = w1v[jp * 4 + 3];
                ull bb = b1v[jp];
                ull hA = bb, hB = bb;
                hA = fma2v(pA0, qa.x, hA); hA = fma2v(pA1, qa.y, hA);
                hA = fma2v(pA2, qb.x, hA); hA = fma2v(pA3, qb.y, hA);
                hA = fma2v(pA4, qc.x, hA); hA = fma2v(pA5, qc.y, hA);
                hA = fma2v(pA6, qd.x, hA); hA = fma2v(pA7, qd.y, hA);
                hB = fma2v(pB0, qa.x, hB); hB = fma2v(pB1, qa.y, hB);
                hB = fma2v(pB2, qb.x, hB); hB = fma2v(pB3, qb.y, hB);
                hB = fma2v(pB4, qc.x, hB); hB = fma2v(pB5, qc.y, hB);
                hB = fma2v(pB6, qd.x, hB); hB = fma2v(pB7, qd.y, hB);
                float hA0, hA1, hB0, hB1;
                upk2(hA, hA0, hA1); upk2(hB, hB0, hB1);
                hA0 = fmaxf(hA0, 0.f); hA1 = fmaxf(hA1, 0.f);
                hB0 = fmaxf(hB0, 0.f); hB1 = fmaxf(hB1, 0.f);
                ull hA0p = pk2(hA0, hA0), hA1p = pk2(hA1, hA1);
                ull hB0p = pk2(hB0, hB0), hB1p = pk2(hB1, hB1);
                ulonglong2 ra = w2v[jp * 4 + 0], rb = w2v[jp * 4 + 1];
                ulonglong2 rc = w2v[jp * 4 + 2], rd = w2v[jp * 4 + 3];
                mA0 = fma2v(hA0p, ra.x, mA0); mA1 = fma2v(hA0p, ra.y, mA1);
                mA2 = fma2v(hA0p, rb.x, mA2); mA3 = fma2v(hA0p, rb.y, mA3);
                mA0 = fma2v(hA1p, rc.x, mA0); mA1 = fma2v(hA1p, rc.y, mA1);
                mA2 = fma2v(hA1p, rd.x, mA2); mA3 = fma2v(hA1p, rd.y, mA3);
                mB0 = fma2v(hB0p, ra.x, mB0); mB1 = fma2v(hB0p, ra.y, mB1);
                mB2 = fma2v(hB0p, rb.x, mB2); mB3 = fma2v(hB0p, rb.y, mB3);
                mB0 = fma2v(hB1p, rc.x, mB0); mB1 = fma2v(hB1p, rc.y, mB1);
                mB2 = fma2v(hB1p, rd.x, mB2); mB3 = fma2v(hB1p, rd.y, mB3);
            }
            pb0[n] = make_ulonglong2(mA0, mB0);   // m0
            pb1[n] = make_ulonglong2(mA1, mB1);   // m1
            pb2[n] = make_ulonglong2(mA2, mB2);   // m2
            pb3[n] = make_ulonglong2(mA3, mB3);   // m3
        }
    }
    __syncthreads();

    // layer-2 Horner, in-place addends (ADD[n] read only by its owning thread):
    GATHER(pb3, pb2, pb2, true); __syncthreads();   // pb2 <- m2 + A m3
    GATHER(pb2, pb1, pb1, true); __syncthreads();   // pb1 <- m1 + A pb2

    // epilogue: out = x + m0 + A pb1 + b2 (same edge pattern; x reloaded via perm)
    {
        float b20 = b2[0], b21 = b2[1];
        float2* ogA = (float2*)out + (size_t)gA * NN;
        float2* ogB = (float2*)out + (size_t)gB * NN;
        const char* pinc = (const char*)pb1;
        #pragma unroll 1
        for (int n = t; n < NN; n += bs) {
            int node = sperm[n];
            ull xA = __ldg(&xgA[node]);
            ull xB = __ldg(&xgB[node]);
            int b = sptr[n], e = sptr[n + 1];
            ulonglong2 m0 = pb0[n];
            ull a0 = m0.x, a1 = m0.y, c0 = 0ull, c1 = 0ull;
            #pragma unroll 1
            for (int q = b; q < e; q += 2) {
                uint32 ss = *(const uint32*)(sedge_s + q);
                float2 wv = *(const float2*)(sedge_w + q);
                ulonglong2 v0 = *(const ulonglong2*)(pinc + (ss & 0xFFFFu));
                ulonglong2 v1 = *(const ulonglong2*)(pinc + (ss >> 16));
                ull ww0 = pk2(wv.x, wv.x), ww1 = pk2(wv.y, wv.y);
                a0 = fma2v(v0.x, ww0, a0); a1 = fma2v(v0.y, ww0, a1);
                c0 = fma2v(v1.x, ww1, c0); c1 = fma2v(v1.y, ww1, c1);
            }
            a0 = add2v(a0, c0); a1 = add2v(a1, c1);
            float ox, oy, xl, xh;
            upk2(a0, ox, oy); upk2(xA, xl, xh);
            ogA[node] = make_float2(xl + ox + b20, xh + oy + b21);
            if (hasB) {
                upk2(a1, ox, oy); upk2(xB, xl, xh);
                ogB[node] = make_float2(xl + ox + b20, xh + oy + b21);
            }
        }
    }
    #undef GATHER
}

// ---------------- launcher ----------------
extern "C" void kernel_launch(void* const* d_in, const int* in_sizes, int n_in,
                              void* d_out, int out_size) {
    const float* x   = (const float*)d_in[0];
    const int*   row = (const int*)  d_in[1];
    const int*   col = (const int*)  d_in[2];
    const float* ew  = (const float*)d_in[3];
    const float* W1  = (const float*)d_in[4];
    const float* b1  = (const float*)d_in[5];
    const float* W2  = (const float*)d_in[6];
    const float* b2  = (const float*)d_in[7];

    const int E = in_sizes[1];
    const int G = in_sizes[0] / (2 * NN);
    const int nCta = (G + 1) / 2;

    cudaFuncSetAttribute(k_main, cudaFuncAttributeMaxDynamicSharedMemorySize, SMEM_BYTES);

    k_main<<<nCta, TPB, SMEM_BYTES>>>(x, row, col, ew, W1, b1, W2, b2,
                                      (float*)d_out, G, E);
}